// round 10
// baseline (speedup 1.0000x reference)
#include <cuda_runtime.h>
#include <cuda_bf16.h>
#include <math.h>
#include <stdint.h>

#define BB 16
#define SS 1024
#define DD 1024
#define CH 32
#define RR 512            // CH*BB rows per chunk
#define NC 32             // SS/CH chunks
#define SB (SS*BB)        // 16384 rows total
#define CSTEPS (RR/16)
#define ETA_F (0.01f*2.0f/(16.0f*1024.0f))

// ---------------- device scratch ----------------
__device__ float g_HT[SB*DD];
__device__ float g_STATE[SB*DD];
__device__ float g_TV[SB*DD];
__device__ float g_PROBE[SB*DD];
__device__ float g_ABASE[SB*DD];   // TV@W0^T - STATE (all chunks)
__device__ float g_PBASE[SB*DD];   // PROBE@W0^T      (all chunks)
__device__ float g_OT[SB*DD];
__device__ float g_X1[SB*DD];
__device__ float g_H2[SB*DD];
__device__ float g_U[SB*DD];
__device__ float g_UW[DD*DD];      // accumulated E^T TV (fp32 master)
__device__ float g_AP[2*RR*DD];
__device__ float g_Gb[NC*RR*RR];
__device__ unsigned g_gbar;        // grid barrier counter
__device__ __nv_bfloat16 g_UWh[DD*DD];
__device__ __nv_bfloat16 g_TVh[SB*DD];
__device__ __nv_bfloat16 g_PRh[SB*DD];
__device__ __nv_bfloat16 g_Eh[RR*DD];
__device__ __nv_bfloat16 g_Eth[DD*RR];
__device__ __nv_bfloat16 g_Hbh[(long)NC*RR*RR];

// ---------------- helpers ----------------
__device__ __forceinline__ float tf32r(float x) {
    unsigned u;
    asm("cvt.rna.tf32.f32 %0, %1;" : "=r"(u) : "f"(x));
    return __uint_as_float(u);
}
__device__ __forceinline__ uint32_t smem_u32(const void* p) {
    uint32_t a;
    asm("{ .reg .u64 t; cvta.to.shared.u64 t, %1; cvt.u32.u64 %0, t; }"
        : "=r"(a) : "l"(p));
    return a;
}
__device__ __forceinline__ void cpa16(uint32_t d, const void* g) {
    asm volatile("cp.async.cg.shared.global [%0], [%1], 16;" :: "r"(d), "l"(g));
}
__device__ __forceinline__ void cpa_commit() {
    asm volatile("cp.async.commit_group;" ::: "memory");
}
__device__ __forceinline__ void mma_tf32(float* c, const unsigned* a, const unsigned* b) {
    asm volatile(
        "mma.sync.aligned.m16n8k8.row.col.f32.tf32.tf32.f32 "
        "{%0,%1,%2,%3}, {%4,%5,%6,%7}, {%8,%9}, {%0,%1,%2,%3};\n"
        : "+f"(c[0]), "+f"(c[1]), "+f"(c[2]), "+f"(c[3])
        : "r"(a[0]), "r"(a[1]), "r"(a[2]), "r"(a[3]), "r"(b[0]), "r"(b[1]));
}
__device__ __forceinline__ void mma_bf16(float* c, const unsigned* a, const unsigned* b) {
    asm volatile(
        "mma.sync.aligned.m16n8k16.row.col.f32.bf16.bf16.f32 "
        "{%0,%1,%2,%3}, {%4,%5,%6,%7}, {%8,%9}, {%0,%1,%2,%3};\n"
        : "+f"(c[0]), "+f"(c[1]), "+f"(c[2]), "+f"(c[3])
        : "r"(a[0]), "r"(a[1]), "r"(a[2]), "r"(a[3]), "r"(b[0]), "r"(b[1]));
}
__device__ __forceinline__ void ldsm4(unsigned& r0, unsigned& r1, unsigned& r2,
                                      unsigned& r3, unsigned addr) {
    asm volatile("ldmatrix.sync.aligned.m8n8.x4.shared.b16 {%0,%1,%2,%3},[%4];"
                 : "=r"(r0), "=r"(r1), "=r"(r2), "=r"(r3) : "r"(addr));
}
__device__ __forceinline__ void ldsm4t(unsigned& r0, unsigned& r1, unsigned& r2,
                                       unsigned& r3, unsigned addr) {
    asm volatile("ldmatrix.sync.aligned.m8n8.x4.trans.shared.b16 {%0,%1,%2,%3},[%4];"
                 : "=r"(r0), "=r"(r1), "=r"(r2), "=r"(r3) : "r"(addr));
}

// software grid barrier (all CTAs co-resident; identical barrier sequence)
__device__ __forceinline__ void gsync(unsigned& epoch) {
    __syncthreads();
    if (threadIdx.x == 0) {
        epoch += gridDim.x;
        __threadfence();
        atomicAdd(&g_gbar, 1u);
        unsigned v;
        for (;;) {
            asm volatile("ld.acquire.gpu.global.u32 %0, [%1];"
                         : "=r"(v) : "l"(&g_gbar) : "memory");
            if (v >= epoch) break;
            __nanosleep(64);
        }
    }
    __syncthreads();
}

// ---------------- elementwise kernels ----------------
__global__ void k_prep(const float* __restrict__ x, const float* __restrict__ a1,
                       float* __restrict__ HT) {
    long i4 = (long)blockIdx.x * blockDim.x + threadIdx.x;
    long flat = i4 * 4;
    int b = (int)(flat / ((long)SS*DD));
    int t = (int)((flat / DD) % SS);
    int d = (int)(flat % DD);
    float4 xv = *(const float4*)(x + flat);
    float4 av = *(const float4*)(a1 + d);
    float4 o;
    o.x = tanhf(av.x * xv.x); o.y = tanhf(av.y * xv.y);
    o.z = tanhf(av.z * xv.z); o.w = tanhf(av.w * xv.w);
    *(float4*)(HT + ((long)(t*BB + b) * DD + d)) = o;
}

__global__ void k_tv(const float* __restrict__ ST, const float* __restrict__ noise,
                     float* __restrict__ TV, __nv_bfloat16* __restrict__ TVh) {
    long i4 = (long)blockIdx.x * blockDim.x + threadIdx.x;
    long flat = i4 * 4;
    int t = (int)(flat / ((long)BB*DD));
    int b = (int)((flat / DD) % BB);
    int d = (int)(flat % DD);
    float4 s = *(const float4*)(ST + flat);
    float4 n = *(const float4*)(noise + ((long)b*SS + t) * DD + d);
    float4 o; o.x = s.x+n.x; o.y = s.y+n.y; o.z = s.z+n.z; o.w = s.w+n.w;
    *(float4*)(TV + flat) = o;
    *(__nv_bfloat162*)(TVh + flat)     = __floats2bfloat162_rn(o.x, o.y);
    *(__nv_bfloat162*)(TVh + flat + 2) = __floats2bfloat162_rn(o.z, o.w);
}

__global__ void k_zero(float* __restrict__ a, __nv_bfloat16* __restrict__ ah) {
    long i = (long)blockIdx.x * blockDim.x + threadIdx.x;
    if (i == 0) g_gbar = 0u;          // reset grid barrier each replay
    *(float4*)(a + i*4) = make_float4(0.f, 0.f, 0.f, 0.f);
    *(float2*)((float*)(ah + i*4)) = make_float2(0.f, 0.f);
}

__global__ void k_x1h2(const float* __restrict__ OT, const float* __restrict__ x,
                       const float* __restrict__ a2,
                       float* __restrict__ X1, float* __restrict__ H2) {
    long i4 = (long)blockIdx.x * blockDim.x + threadIdx.x;
    long flat = i4 * 4;
    int b = (int)(flat / ((long)SS*DD));
    int t = (int)((flat / DD) % SS);
    int d = (int)(flat % DD);
    float4 ro = *(const float4*)(OT + ((long)(t*BB + b) * DD + d));
    float4 xv = *(const float4*)(x + flat);
    float4 av = *(const float4*)(a2 + d);
    float4 x1; x1.x = ro.x+xv.x; x1.y = ro.y+xv.y; x1.z = ro.z+xv.z; x1.w = ro.w+xv.w;
    *(float4*)(X1 + flat) = x1;
    float4 h; h.x = tanhf(av.x*x1.x); h.y = tanhf(av.y*x1.y);
    h.z = tanhf(av.z*x1.z); h.w = tanhf(av.w*x1.w);
    *(float4*)(H2 + flat) = h;
}

// ---------------- tf32 tensor-core GEMM (unchanged, proven) ----------
// MODE: 0 plain  5 gelu  6 C=P1*acc+P2  7 plain + bf16 copy->P2  8 C=acc-P1
template<int BM,int BN,int MW,int NW,int MODE>
__global__ void __launch_bounds__(MW*NW*32, 2)
gemm_t(const float* __restrict__ A, int lda,
       const float* __restrict__ B, int ldb,
       float* __restrict__ C, int ldc, int K,
       const float* __restrict__ P1, const float* __restrict__ P2)
{
    constexpr int BK  = 16;
    constexpr int BKp = 20;
    constexpr int T   = MW*NW*32;
    constexpr int WM  = BM/MW, WN = BN/NW;
    constexpr int MT  = WM/16, NT = WN/8;
    constexpr int LPA = BM*BK/(4*T);
    constexpr int LPB = BN*BK/(4*T);

    const int m0 = blockIdx.y * BM, n0 = blockIdx.x * BN;

    __shared__ __align__(16) float As[2][BM][BKp];
    __shared__ __align__(16) float Bs[2][BN][BKp];

    const int tid  = threadIdx.x;
    const int lane = tid & 31;
    const int wid  = tid >> 5;
    const int wm   = wid / NW, wn = wid % NW;
    const int mw0  = wm * WM, nw0 = wn * WN;
    const int qr   = lane >> 2;
    const int qc   = lane & 3;
    const int lr   = lane & 7;
    const int aBase = (mw0 + lr + ((lane>>3)&1)*8) * BKp + ((lane>>4)&1)*4;
    const int bBase = (nw0 + lr + ((lane>>4)&1)*8) * BKp + ((lane>>3)&1)*4;

    float acc[MT][NT][4];
    #pragma unroll
    for (int i = 0; i < MT; ++i)
        #pragma unroll
        for (int j = 0; j < NT; ++j)
            #pragma unroll
            for (int q = 0; q < 4; ++q) acc[i][j][q] = 0.f;

    const int ktiles = K / BK;
    float4 pa[LPA], pb[LPB];

    auto gload = [&](int k0) {
        #pragma unroll
        for (int p = 0; p < LPA; ++p) {
            const int idx = tid + p*T;
            const int am = idx / (BK/4), akq = idx % (BK/4);
            pa[p] = *(const float4*)(A + (long)(m0 + am) * lda + k0 + 4*akq);
        }
        #pragma unroll
        for (int p = 0; p < LPB; ++p) {
            const int idx = tid + p*T;
            const int bn = idx / (BK/4), bkq = idx % (BK/4);
            pb[p] = *(const float4*)(B + (long)(n0 + bn) * ldb + k0 + 4*bkq);
        }
    };
    auto sstore = [&](int s) {
        #pragma unroll
        for (int p = 0; p < LPA; ++p) {
            const int idx = tid + p*T;
            const int am = idx / (BK/4), akq = idx % (BK/4);
            float4 w = make_float4(tf32r(pa[p].x), tf32r(pa[p].y),
                                   tf32r(pa[p].z), tf32r(pa[p].w));
            *(float4*)&As[s][am][4*akq] = w;
        }
        #pragma unroll
        for (int p = 0; p < LPB; ++p) {
            const int idx = tid + p*T;
            const int bn = idx / (BK/4), bkq = idx % (BK/4);
            float4 w = make_float4(tf32r(pb[p].x), tf32r(pb[p].y),
                                   tf32r(pb[p].z), tf32r(pb[p].w));
            *(float4*)&Bs[s][bn][4*bkq] = w;
        }
    };
    auto compute = [&](int s) {
        const unsigned sA = (unsigned)__cvta_generic_to_shared(&As[s][0][0]);
        const unsigned sB = (unsigned)__cvta_generic_to_shared(&Bs[s][0][0]);
        #pragma unroll
        for (int ks = 0; ks < BK; ks += 8) {
            unsigned af[MT][4];
            #pragma unroll
            for (int im = 0; im < MT; ++im)
                ldsm4(af[im][0], af[im][1], af[im][2], af[im][3],
                      sA + 4u*(aBase + im*16*BKp + ks));
            unsigned bf[NT][2];
            #pragma unroll
            for (int jp = 0; jp < NT/2; ++jp) {
                unsigned r0, r1, r2, r3;
                ldsm4(r0, r1, r2, r3, sB + 4u*(bBase + jp*16*BKp + ks));
                bf[2*jp][0] = r0; bf[2*jp][1] = r1;
                bf[2*jp+1][0] = r2; bf[2*jp+1][1] = r3;
            }
            #pragma unroll
            for (int im = 0; im < MT; ++im)
                #pragma unroll
                for (int jn = 0; jn < NT; ++jn)
                    mma_tf32(acc[im][jn], af[im], bf[jn]);
        }
    };

    gload(0);
    sstore(0);
    __syncthreads();

    for (int kt = 0; kt < ktiles; ++kt) {
        const bool more = (kt + 1 < ktiles);
        if (more) gload((kt+1)*BK);
        compute(kt & 1);
        if (more) sstore((kt+1) & 1);
        __syncthreads();
    }

    #pragma unroll
    for (int im = 0; im < MT; ++im) {
        #pragma unroll
        for (int jn = 0; jn < NT; ++jn) {
            #pragma unroll
            for (int h = 0; h < 2; ++h) {
                const int m = m0 + mw0 + im*16 + qr + h*8;
                const int n = n0 + nw0 + jn*8 + qc*2;
                const long ci = (long)m * ldc + n;
                float v0 = acc[im][jn][h*2 + 0];
                float v1 = acc[im][jn][h*2 + 1];
                if (MODE == 0) {
                    C[ci] = v0; C[ci+1] = v1;
                } else if (MODE == 5) {
                    C[ci]   = 0.5f * v0 * (1.f + erff(v0 * 0.70710678118654752f));
                    C[ci+1] = 0.5f * v1 * (1.f + erff(v1 * 0.70710678118654752f));
                } else if (MODE == 6) {
                    C[ci]   = P1[ci]   * v0 + P2[ci];
                    C[ci+1] = P1[ci+1] * v1 + P2[ci+1];
                } else if (MODE == 7) {
                    C[ci] = v0; C[ci+1] = v1;
                    __nv_bfloat16* Cb = (__nv_bfloat16*)P2;
                    *(__nv_bfloat162*)(Cb + ci) = __floats2bfloat162_rn(v0, v1);
                } else if (MODE == 8) {
                    float2 p = *(const float2*)(P1 + ci);
                    C[ci]   = v0 - p.x;
                    C[ci+1] = v1 - p.y;
                }
            }
        }
    }
}

// ---------------- pipelined bf16 core (cp.async, 4 stages) ----------
// Tile 128x64, 256 threads, 8 warps (4m x 2n), warp tile 32x32.
// OPA: 0 = A[M,K]; 2 = dual-source rows. OPB: 0 = B[N,K]; 1 = B[K,N].
// MODE: 2 tril mask  3 C=P1a-ETA*acc (tril-K)  8 C=P1dual-ETA*acc  9 C+=acc & bf16->Ch
#define HSTG 9216   // 6144 A + 3072 B per stage
#define HSM  (4*HSTG)

template<int OPA,int OPB,int MODE,int OUTT>
__device__ __forceinline__ void hcore(
    int m0, int n0,
    const __nv_bfloat16* A, const __nv_bfloat16* A2, long lda,
    const __nv_bfloat16* B, long ldb,
    float* C, __nv_bfloat16* Ch, long ldc, int K,
    const float* P1a, const float* P1b, char* sm)
{
    constexpr int BM = 128, BK = 16;
    const int tid = threadIdx.x, lane = tid & 31, wid = tid >> 5;
    const int wm = wid >> 1, wn = wid & 1;
    const int mw0 = wm * 32, nw0 = wn * 32;
    const int qr = lane >> 2, qc = lane & 3;
    const uint32_t sbase = smem_u32(sm);

    float acc[2][4][4];
    #pragma unroll
    for (int i = 0; i < 2; ++i)
        #pragma unroll
        for (int j = 0; j < 4; ++j)
            #pragma unroll
            for (int q = 0; q < 4; ++q) acc[i][j][q] = 0.f;

    int Kl = K;
    if (MODE == 3) { int t = m0 + BM; Kl = t < K ? t : K; }
    const int ktiles = Kl / BK;

    const int arow = tid >> 1, ahalf = tid & 1;
    const int mg = m0 + arow;
    const __nv_bfloat16* Ar;
    if (OPA == 2) Ar = (mg < RR) ? (A + (long)mg * lda)
                                 : (A2 + (long)(mg - RR) * lda);
    else          Ar = A + (long)mg * lda;

    auto fill = [&](int kt) {
        if (kt < ktiles) {
            const long k0 = (long)kt * BK;
            const uint32_t as = sbase + (kt & 3) * HSTG;
            const uint32_t bs = as + 6144;
            cpa16(as + arow*48 + ahalf*16, Ar + k0 + ahalf*8);
            if (tid < 128) {
                if (OPB == 0) {
                    const int r = tid >> 1, h = tid & 1;
                    cpa16(bs + r*48 + h*16, B + (long)(n0 + r)*ldb + k0 + h*8);
                } else {
                    const int kk = tid >> 3, nc = tid & 7;
                    cpa16(bs + kk*144 + nc*16, B + (k0 + kk)*ldb + n0 + nc*8);
                }
            }
        }
        cpa_commit();
    };
    auto compute = [&](int kt) {
        const uint32_t sA = sbase + (kt & 3) * HSTG;
        const uint32_t sB = sA + 6144;
        const int g = lane >> 3;
        unsigned af[2][4];
        #pragma unroll
        for (int im = 0; im < 2; ++im) {
            const int row = mw0 + im*16 + (g & 1)*8 + (lane & 7);
            const int kb = (g >> 1)*8;
            ldsm4(af[im][0], af[im][1], af[im][2], af[im][3],
                  sA + (unsigned)(row*48 + kb*2));
        }
        unsigned bf[4][2];
        #pragma unroll
        for (int jp = 0; jp < 2; ++jp) {
            unsigned r0, r1, r2, r3;
            if (OPB == 0) {
                const int row = nw0 + jp*16 + (g >> 1)*8 + (lane & 7);
                const int kb = (g & 1)*8;
                ldsm4(r0, r1, r2, r3, sB + (unsigned)(row*48 + kb*2));
            } else {
                const int krow = (g & 1)*8 + (lane & 7);
                const int col = nw0 + jp*16 + (g >> 1)*8;
                ldsm4t(r0, r1, r2, r3, sB + (unsigned)(krow*144 + col*2));
            }
            bf[2*jp][0] = r0; bf[2*jp][1] = r1;
            bf[2*jp+1][0] = r2; bf[2*jp+1][1] = r3;
        }
        #pragma unroll
        for (int im = 0; im < 2; ++im)
            #pragma unroll
            for (int jn = 0; jn < 4; ++jn)
                mma_bf16(acc[im][jn], af[im], bf[jn]);
    };

    fill(0); fill(1); fill(2);
    for (int kt = 0; kt < ktiles; ++kt) {
        asm volatile("cp.async.wait_group 2;" ::: "memory");
        __syncthreads();
        fill(kt + 3);
        compute(kt);
    }
    asm volatile("cp.async.wait_group 0;" ::: "memory");

    #pragma unroll
    for (int im = 0; im < 2; ++im) {
        #pragma unroll
        for (int jn = 0; jn < 4; ++jn) {
            #pragma unroll
            for (int h = 0; h < 2; ++h) {
                const int m = m0 + mw0 + im*16 + qr + h*8;
                const int n = n0 + nw0 + jn*8 + qc*2;
                const long ci = (long)m * ldc + n;
                float v0 = acc[im][jn][h*2 + 0];
                float v1 = acc[im][jn][h*2 + 1];
                if (MODE == 2) {
                    const bool z = ((n >> 4) > (m >> 4));
                    if (z) { v0 = 0.f; v1 = 0.f; }
                    if (OUTT == 1)
                        *(__nv_bfloat162*)(Ch + ci) = __floats2bfloat162_rn(v0, v1);
                    else { C[ci] = v0; C[ci+1] = v1; }
                } else if (MODE == 3) {
                    float2 p = *(const float2*)(P1a + (long)m * ldc + n);
                    C[ci]   = p.x - ETA_F * v0;
                    C[ci+1] = p.y - ETA_F * v1;
                } else if (MODE == 8) {
                    const float* Pp = (m < RR) ? (P1a + (long)m * ldc + n)
                                               : (P1b + (long)(m - RR) * ldc + n);
                    float2 p = *(const float2*)Pp;
                    C[ci]   = p.x - ETA_F * v0;
                    C[ci+1] = p.y - ETA_F * v1;
                } else if (MODE == 9) {
                    float2 c = *(const float2*)(C + ci);
                    float w0 = c.x + v0, w1 = c.y + v1;
                    C[ci] = w0; C[ci+1] = w1;
                    *(__nv_bfloat162*)(Ch + ci) = __floats2bfloat162_rn(w0, w1);
                }
            }
        }
    }
}

// Gram wrappers (batched over z, block-tril skip) — prologue only
template<int OUTT>
__global__ void __launch_bounds__(256) k_gram(
    const __nv_bfloat16* __restrict__ Aall, const __nv_bfloat16* __restrict__ Ball,
    float* __restrict__ Cf, __nv_bfloat16* __restrict__ Cbh)
{
    const int m0 = blockIdx.y * 128, n0 = blockIdx.x * 64;
    if (n0 >= m0 + 128) return;
    __shared__ __align__(16) char sm[HSM];
    const long z = blockIdx.z;
    hcore<0,0,2,OUTT>(m0, n0,
        Aall + z*RR*DD, nullptr, DD, Ball + z*RR*DD, DD,
        (OUTT == 0) ? (Cf + z*RR*RR) : nullptr,
        (OUTT == 1) ? (Cbh + z*RR*RR) : nullptr,
        RR, DD, nullptr, nullptr, sm);
}

// ---------------- forward substitution body (device fn, smem passed in) ----
__device__ void solve_body(const float* __restrict__ A, const float* __restrict__ G,
                           __nv_bfloat16* __restrict__ Eh,
                           __nv_bfloat16* __restrict__ Eth, char* smraw) {
    float (*Es)[RR + 4] = (float (*)[RR + 4])smraw;
    const int j0 = blockIdx.x * 16;
    const int tid = threadIdx.x;
    const int r = tid >> 4, j = tid & 15;
    #pragma unroll
    for (int i = 0; i < CSTEPS; ++i) {
        int row = i*16 + r;
        Es[j][row] = A[(long)row * DD + j0 + j];
    }
    __syncthreads();
    for (int t = 1; t < CSTEPS; ++t) {
        const int row = t*16 + r;
        const float* Gr = G + (long)row * RR;
        const int kmax = t * 16;
        float sx=0.f, sy=0.f, sz=0.f, sw=0.f;
        for (int k = 0; k < kmax; k += 4) {
            float4 g = *(const float4*)(Gr + k);
            float4 e = *(const float4*)&Es[j][k];
            sx = fmaf(g.x, e.x, sx); sy = fmaf(g.y, e.y, sy);
            sz = fmaf(g.z, e.z, sz); sw = fmaf(g.w, e.w, sw);
        }
        float v = Es[j][row] - ETA_F * ((sx+sy)+(sz+sw));
        Es[j][row] = v;
        __syncthreads();
    }
    #pragma unroll
    for (int i = 0; i < CSTEPS; ++i) {
        int row = i*16 + r;
        __nv_bfloat16 hv = __float2bfloat16(Es[j][row]);
        Eh[(long)row * DD + j0 + j] = hv;
        Eth[(long)(j0 + j) * RR + row] = hv;
    }
}

// ---------------- persistent chunk-loop kernel ----------------
__global__ void __launch_bounds__(256) k_loop(
    const __nv_bfloat16* __restrict__ TVh, const __nv_bfloat16* __restrict__ PRh,
    const float* __restrict__ AB, const float* __restrict__ PB,
    const float* __restrict__ Gb, const __nv_bfloat16* __restrict__ Hbh,
    float* __restrict__ AP, float* __restrict__ OT,
    float* __restrict__ UW, __nv_bfloat16* __restrict__ UWh,
    __nv_bfloat16* __restrict__ Eh, __nv_bfloat16* __restrict__ Eth)
{
    __shared__ __align__(16) char sm[HSM];
    unsigned epoch = 0;
    const int nb = gridDim.x;

    for (int c = 0; c < NC; ++c) {
        const __nv_bfloat16* TVhc = TVh + (long)c*RR*DD;
        const __nv_bfloat16* PRhc = PRh + (long)c*RR*DD;
        const float* ABc = AB + (long)c*RR*DD;
        const float* PBc = PB + (long)c*RR*DD;
        const float* Asolve;
        const float* P0;

        if (c == 0) {
            Asolve = ABc;
            P0 = PBc;
        } else {
            // phase A: AP = [ABc;PBc] - ETA * [TVc;PRc] @ UW^T  (128 tiles)
            for (int t = blockIdx.x; t < 128; t += nb) {
                const int m0 = (t & 7) * 128, n0 = (t >> 3) * 64;
                hcore<2,0,8,0>(m0, n0, TVhc, PRhc, DD, UWh, DD,
                               AP, nullptr, DD, DD, ABc, PBc, sm);
            }
            gsync(epoch);
            Asolve = AP;
            P0 = AP + (long)RR*DD;
        }

        // phase B: forward substitution (CTAs 0..63)
        if (blockIdx.x < 64)
            solve_body(Asolve, Gb + (long)c*RR*RR, Eh, Eth, sm);
        gsync(epoch);

        // phase C: readout (64 tiles) + UW update (128 tiles)
        for (int t = blockIdx.x; t < 192; t += nb) {
            if (t < 64) {
                const int m0 = (t & 3) * 128, n0 = (t >> 2) * 64;
                hcore<0,1,3,0>(m0, n0, Hbh + (long)c*RR*RR, nullptr, RR, Eh, DD,
                               OT + (long)c*RR*DD, nullptr, DD, RR, P0, nullptr, sm);
            } else {
                const int tt = t - 64;
                const int m0 = (tt & 7) * 128, n0 = (tt >> 3) * 64;
                hcore<0,1,9,0>(m0, n0, Eth, nullptr, RR, TVhc, DD,
                               UW, UWh, DD, RR, nullptr, nullptr, sm);
            }
        }
        gsync(epoch);
    }
}

// ---------------- host side ----------------
extern "C" void kernel_launch(void* const* d_in, const int* in_sizes, int n_in,
                              void* d_out, int out_size) {
    const float* x      = (const float*)d_in[0];
    const float* noise  = (const float*)d_in[1];
    const float* alpha1 = (const float*)d_in[2];
    const float* alpha2 = (const float*)d_in[3];
    const float* W_map  = (const float*)d_in[4];
    const float* W_st   = (const float*)d_in[5];
    const float* W_pr   = (const float*)d_in[6];
    const float* W_p1   = (const float*)d_in[7];
    const float* W_p2   = (const float*)d_in[8];
    float* out = (float*)d_out;

    float *HT, *ST, *TV, *PR, *AB, *PB, *OT, *X1, *H2, *U, *UW, *AP, *Gb;
    __nv_bfloat16 *UWh, *TVh, *PRh, *Eh, *Eth, *Hbh;
    cudaGetSymbolAddress((void**)&HT, g_HT);
    cudaGetSymbolAddress((void**)&ST, g_STATE);
    cudaGetSymbolAddress((void**)&TV, g_TV);
    cudaGetSymbolAddress((void**)&PR, g_PROBE);
    cudaGetSymbolAddress((void**)&AB, g_ABASE);
    cudaGetSymbolAddress((void**)&PB, g_PBASE);
    cudaGetSymbolAddress((void**)&OT, g_OT);
    cudaGetSymbolAddress((void**)&X1, g_X1);
    cudaGetSymbolAddress((void**)&H2, g_H2);
    cudaGetSymbolAddress((void**)&U,  g_U);
    cudaGetSymbolAddress((void**)&UW, g_UW);
    cudaGetSymbolAddress((void**)&AP, g_AP);
    cudaGetSymbolAddress((void**)&Gb, g_Gb);
    cudaGetSymbolAddress((void**)&UWh, g_UWh);
    cudaGetSymbolAddress((void**)&TVh, g_TVh);
    cudaGetSymbolAddress((void**)&PRh, g_PRh);
    cudaGetSymbolAddress((void**)&Eh,  g_Eh);
    cudaGetSymbolAddress((void**)&Eth, g_Eth);
    cudaGetSymbolAddress((void**)&Hbh, g_Hbh);

    int sms = 148;
    cudaDeviceGetAttribute(&sms, cudaDevAttrMultiProcessorCount, 0);

    const int EW_BLKS = (SB*DD/4) / 256;

    // 0: h = tanh(alpha1*x), time-major
    k_prep<<<EW_BLKS, 256>>>(x, alpha1, HT);
    // 1: STATE = HT@Wst^T (tf32)
    gemm_t<128,128,2,4,0><<<dim3(DD/128, SB/128), 256>>>(
        HT, DD, W_st, DD, ST, DD, DD, nullptr, nullptr);
    // 2: TV = STATE + noise (fp32 + bf16)
    k_tv<<<EW_BLKS, 256>>>(ST, noise, TV, TVh);
    // 3: batched block-tril Gram (pipelined bf16)
    k_gram<0><<<dim3(RR/64, RR/128, NC), 256>>>(TVh, TVh, Gb, nullptr);
    // 4: PROBE = HT@Wpr^T (tf32 + bf16 copy)
    gemm_t<128,128,2,4,7><<<dim3(DD/128, SB/128), 256>>>(
        HT, DD, W_pr, DD, PR, DD, DD, nullptr, (const float*)PRh);
    // 5: ABASE = TV@W0^T - STATE (tf32)
    gemm_t<128,128,2,4,8><<<dim3(DD/128, SB/128), 256>>>(
        TV, DD, W_map, DD, AB, DD, DD, ST, nullptr);
    // 6: PBASE = PROBE@W0^T (tf32)
    gemm_t<128,128,2,4,0><<<dim3(DD/128, SB/128), 256>>>(
        PR, DD, W_map, DD, PB, DD, DD, nullptr, nullptr);
    // 7: cross-Gram -> Hbh (bf16)
    k_gram<1><<<dim3(RR/64, RR/128, NC), 256>>>(PRh, TVh, nullptr, Hbh);
    // 8: zero UW accumulator + grid-barrier counter
    k_zero<<<(DD*DD/4)/256, 256>>>(UW, UWh);

    // 9: persistent chunk loop (one kernel, software grid barriers)
    k_loop<<<sms, 256>>>(TVh, PRh, AB, PB, Gb, Hbh, AP, OT, UW, UWh, Eh, Eth);

    // x1 / h2
    k_x1h2<<<EW_BLKS, 256>>>(OT, x, alpha2, X1, H2);
    // U = gelu(h2 @ Wp1^T)   (tf32)
    gemm_t<128,128,2,4,5><<<dim3(DD/128, SB/128), 256>>>(
        H2, DD, W_p1, DD, U, DD, DD, nullptr, nullptr);
    // out = U * (h2 @ Wp2^T) + X1   (tf32)
    gemm_t<128,128,2,4,6><<<dim3(DD/128, SB/128), 256>>>(
        H2, DD, W_p2, DD, out, DD, DD, U, X1);
}

// round 11
// speedup vs baseline: 1.0468x; 1.0468x over previous
#include <cuda_runtime.h>
#include <cuda_bf16.h>
#include <math.h>
#include <stdint.h>

#define BB 16
#define SS 1024
#define DD 1024
#define CH 32
#define RR 512            // CH*BB rows per chunk
#define NC 32             // SS/CH chunks
#define SB (SS*BB)        // 16384 rows total
#define CSTEPS (RR/16)
#define ETA_F (0.01f*2.0f/(16.0f*1024.0f))

// ---------------- device scratch ----------------
__device__ float g_HT[SB*DD];
__device__ float g_STATE[SB*DD];
__device__ float g_TV[SB*DD];
__device__ float g_PROBE[SB*DD];
__device__ float g_ABASE[SB*DD];   // TV@W0^T - STATE (all chunks)
__device__ float g_PBASE[SB*DD];   // PROBE@W0^T      (all chunks)
__device__ float g_OT[SB*DD];
__device__ float g_X1[SB*DD];
__device__ float g_H2[SB*DD];
__device__ float g_U[SB*DD];
__device__ float g_UW[DD*DD];      // accumulated E^T TV (fp32 master)
__device__ float g_AP[2*RR*DD];
__device__ float g_Gb[NC*RR*RR];
__device__ __nv_bfloat16 g_UWh[DD*DD];
__device__ __nv_bfloat16 g_TVh[SB*DD];
__device__ __nv_bfloat16 g_PRh[SB*DD];
__device__ __nv_bfloat16 g_Eh[RR*DD];
__device__ __nv_bfloat16 g_Eth[DD*RR];
__device__ __nv_bfloat16 g_Hbh[(long)NC*RR*RR];

// ---------------- helpers ----------------
__device__ __forceinline__ float tf32r(float x) {
    unsigned u;
    asm("cvt.rna.tf32.f32 %0, %1;" : "=r"(u) : "f"(x));
    return __uint_as_float(u);
}
__device__ __forceinline__ uint32_t smem_u32(const void* p) {
    uint32_t a;
    asm("{ .reg .u64 t; cvta.to.shared.u64 t, %1; cvt.u32.u64 %0, t; }"
        : "=r"(a) : "l"(p));
    return a;
}
__device__ __forceinline__ void cpa16(uint32_t d, const void* g) {
    asm volatile("cp.async.cg.shared.global [%0], [%1], 16;" :: "r"(d), "l"(g));
}
__device__ __forceinline__ void cpa_commit() {
    asm volatile("cp.async.commit_group;" ::: "memory");
}
__device__ __forceinline__ void mma_tf32(float* c, const unsigned* a, const unsigned* b) {
    asm volatile(
        "mma.sync.aligned.m16n8k8.row.col.f32.tf32.tf32.f32 "
        "{%0,%1,%2,%3}, {%4,%5,%6,%7}, {%8,%9}, {%0,%1,%2,%3};\n"
        : "+f"(c[0]), "+f"(c[1]), "+f"(c[2]), "+f"(c[3])
        : "r"(a[0]), "r"(a[1]), "r"(a[2]), "r"(a[3]), "r"(b[0]), "r"(b[1]));
}
__device__ __forceinline__ void mma_bf16(float* c, const unsigned* a, const unsigned* b) {
    asm volatile(
        "mma.sync.aligned.m16n8k16.row.col.f32.bf16.bf16.f32 "
        "{%0,%1,%2,%3}, {%4,%5,%6,%7}, {%8,%9}, {%0,%1,%2,%3};\n"
        : "+f"(c[0]), "+f"(c[1]), "+f"(c[2]), "+f"(c[3])
        : "r"(a[0]), "r"(a[1]), "r"(a[2]), "r"(a[3]), "r"(b[0]), "r"(b[1]));
}
__device__ __forceinline__ void ldsm4(unsigned& r0, unsigned& r1, unsigned& r2,
                                      unsigned& r3, unsigned addr) {
    asm volatile("ldmatrix.sync.aligned.m8n8.x4.shared.b16 {%0,%1,%2,%3},[%4];"
                 : "=r"(r0), "=r"(r1), "=r"(r2), "=r"(r3) : "r"(addr));
}
__device__ __forceinline__ void ldsm4t(unsigned& r0, unsigned& r1, unsigned& r2,
                                       unsigned& r3, unsigned addr) {
    asm volatile("ldmatrix.sync.aligned.m8n8.x4.trans.shared.b16 {%0,%1,%2,%3},[%4];"
                 : "=r"(r0), "=r"(r1), "=r"(r2), "=r"(r3) : "r"(addr));
}

// ---------------- elementwise kernels ----------------
__global__ void k_prep(const float* __restrict__ x, const float* __restrict__ a1,
                       float* __restrict__ HT) {
    long i4 = (long)blockIdx.x * blockDim.x + threadIdx.x;
    long flat = i4 * 4;
    int b = (int)(flat / ((long)SS*DD));
    int t = (int)((flat / DD) % SS);
    int d = (int)(flat % DD);
    float4 xv = *(const float4*)(x + flat);
    float4 av = *(const float4*)(a1 + d);
    float4 o;
    o.x = tanhf(av.x * xv.x); o.y = tanhf(av.y * xv.y);
    o.z = tanhf(av.z * xv.z); o.w = tanhf(av.w * xv.w);
    *(float4*)(HT + ((long)(t*BB + b) * DD + d)) = o;
}

__global__ void k_tv(const float* __restrict__ ST, const float* __restrict__ noise,
                     float* __restrict__ TV, __nv_bfloat16* __restrict__ TVh) {
    long i4 = (long)blockIdx.x * blockDim.x + threadIdx.x;
    long flat = i4 * 4;
    int t = (int)(flat / ((long)BB*DD));
    int b = (int)((flat / DD) % BB);
    int d = (int)(flat % DD);
    float4 s = *(const float4*)(ST + flat);
    float4 n = *(const float4*)(noise + ((long)b*SS + t) * DD + d);
    float4 o; o.x = s.x+n.x; o.y = s.y+n.y; o.z = s.z+n.z; o.w = s.w+n.w;
    *(float4*)(TV + flat) = o;
    *(__nv_bfloat162*)(TVh + flat)     = __floats2bfloat162_rn(o.x, o.y);
    *(__nv_bfloat162*)(TVh + flat + 2) = __floats2bfloat162_rn(o.z, o.w);
}

__global__ void k_zero(float* __restrict__ a, __nv_bfloat16* __restrict__ ah) {
    long i = (long)blockIdx.x * blockDim.x + threadIdx.x;
    *(float4*)(a + i*4) = make_float4(0.f, 0.f, 0.f, 0.f);
    *(float2*)((float*)(ah + i*4)) = make_float2(0.f, 0.f);
}

__global__ void k_x1h2(const float* __restrict__ OT, const float* __restrict__ x,
                       const float* __restrict__ a2,
                       float* __restrict__ X1, float* __restrict__ H2) {
    long i4 = (long)blockIdx.x * blockDim.x + threadIdx.x;
    long flat = i4 * 4;
    int b = (int)(flat / ((long)SS*DD));
    int t = (int)((flat / DD) % SS);
    int d = (int)(flat % DD);
    float4 ro = *(const float4*)(OT + ((long)(t*BB + b) * DD + d));
    float4 xv = *(const float4*)(x + flat);
    float4 av = *(const float4*)(a2 + d);
    float4 x1; x1.x = ro.x+xv.x; x1.y = ro.y+xv.y; x1.z = ro.z+xv.z; x1.w = ro.w+xv.w;
    *(float4*)(X1 + flat) = x1;
    float4 h; h.x = tanhf(av.x*x1.x); h.y = tanhf(av.y*x1.y);
    h.z = tanhf(av.z*x1.z); h.w = tanhf(av.w*x1.w);
    *(float4*)(H2 + flat) = h;
}

// ---------------- forward substitution (RR=512, 32 steps) ----------------
__global__ void __launch_bounds__(256) solve_k(const float* __restrict__ A,
                                               const float* __restrict__ G,
                                               __nv_bfloat16* __restrict__ Eh,
                                               __nv_bfloat16* __restrict__ Eth) {
    __shared__ __align__(16) float Es[16][RR + 4];
    const int j0 = blockIdx.x * 16;
    const int tid = threadIdx.x;
    const int r = tid >> 4, j = tid & 15;
    #pragma unroll
    for (int i = 0; i < CSTEPS; ++i) {
        int row = i*16 + r;
        Es[j][row] = A[(long)row * DD + j0 + j];
    }
    __syncthreads();
    for (int t = 1; t < CSTEPS; ++t) {
        const int row = t*16 + r;
        const float* Gr = G + (long)row * RR;
        const int kmax = t * 16;
        float sx=0.f, sy=0.f, sz=0.f, sw=0.f;
        for (int k = 0; k < kmax; k += 4) {
            float4 g = *(const float4*)(Gr + k);
            float4 e = *(const float4*)&Es[j][k];
            sx = fmaf(g.x, e.x, sx); sy = fmaf(g.y, e.y, sy);
            sz = fmaf(g.z, e.z, sz); sw = fmaf(g.w, e.w, sw);
        }
        float v = Es[j][row] - ETA_F * ((sx+sy)+(sz+sw));
        Es[j][row] = v;
        __syncthreads();
    }
    #pragma unroll
    for (int i = 0; i < CSTEPS; ++i) {
        int row = i*16 + r;
        __nv_bfloat16 hv = __float2bfloat16(Es[j][row]);
        Eh[(long)row * DD + j0 + j] = hv;
        Eth[(long)(j0 + j) * RR + row] = hv;
    }
}

// ---------------- tf32 tensor-core GEMM (unchanged, proven) ----------
// MODE: 0 plain  5 gelu  6 C=P1*acc+P2  7 plain + bf16 copy->P2  8 C=acc-P1
template<int BM,int BN,int MW,int NW,int MODE>
__global__ void __launch_bounds__(MW*NW*32, 2)
gemm_t(const float* __restrict__ A, int lda,
       const float* __restrict__ B, int ldb,
       float* __restrict__ C, int ldc, int K,
       const float* __restrict__ P1, const float* __restrict__ P2)
{
    constexpr int BK  = 16;
    constexpr int BKp = 20;
    constexpr int T   = MW*NW*32;
    constexpr int WM  = BM/MW, WN = BN/NW;
    constexpr int MT  = WM/16, NT = WN/8;
    constexpr int LPA = BM*BK/(4*T);
    constexpr int LPB = BN*BK/(4*T);

    const int m0 = blockIdx.y * BM, n0 = blockIdx.x * BN;

    __shared__ __align__(16) float As[2][BM][BKp];
    __shared__ __align__(16) float Bs[2][BN][BKp];

    const int tid  = threadIdx.x;
    const int lane = tid & 31;
    const int wid  = tid >> 5;
    const int wm   = wid / NW, wn = wid % NW;
    const int mw0  = wm * WM, nw0 = wn * WN;
    const int qr   = lane >> 2;
    const int qc   = lane & 3;
    const int lr   = lane & 7;
    const int aBase = (mw0 + lr + ((lane>>3)&1)*8) * BKp + ((lane>>4)&1)*4;
    const int bBase = (nw0 + lr + ((lane>>4)&1)*8) * BKp + ((lane>>3)&1)*4;

    float acc[MT][NT][4];
    #pragma unroll
    for (int i = 0; i < MT; ++i)
        #pragma unroll
        for (int j = 0; j < NT; ++j)
            #pragma unroll
            for (int q = 0; q < 4; ++q) acc[i][j][q] = 0.f;

    const int ktiles = K / BK;
    float4 pa[LPA], pb[LPB];

    auto gload = [&](int k0) {
        #pragma unroll
        for (int p = 0; p < LPA; ++p) {
            const int idx = tid + p*T;
            const int am = idx / (BK/4), akq = idx % (BK/4);
            pa[p] = *(const float4*)(A + (long)(m0 + am) * lda + k0 + 4*akq);
        }
        #pragma unroll
        for (int p = 0; p < LPB; ++p) {
            const int idx = tid + p*T;
            const int bn = idx / (BK/4), bkq = idx % (BK/4);
            pb[p] = *(const float4*)(B + (long)(n0 + bn) * ldb + k0 + 4*bkq);
        }
    };
    auto sstore = [&](int s) {
        #pragma unroll
        for (int p = 0; p < LPA; ++p) {
            const int idx = tid + p*T;
            const int am = idx / (BK/4), akq = idx % (BK/4);
            float4 w = make_float4(tf32r(pa[p].x), tf32r(pa[p].y),
                                   tf32r(pa[p].z), tf32r(pa[p].w));
            *(float4*)&As[s][am][4*akq] = w;
        }
        #pragma unroll
        for (int p = 0; p < LPB; ++p) {
            const int idx = tid + p*T;
            const int bn = idx / (BK/4), bkq = idx % (BK/4);
            float4 w = make_float4(tf32r(pb[p].x), tf32r(pb[p].y),
                                   tf32r(pb[p].z), tf32r(pb[p].w));
            *(float4*)&Bs[s][bn][4*bkq] = w;
        }
    };
    auto compute = [&](int s) {
        const unsigned sA = (unsigned)__cvta_generic_to_shared(&As[s][0][0]);
        const unsigned sB = (unsigned)__cvta_generic_to_shared(&Bs[s][0][0]);
        #pragma unroll
        for (int ks = 0; ks < BK; ks += 8) {
            unsigned af[MT][4];
            #pragma unroll
            for (int im = 0; im < MT; ++im)
                ldsm4(af[im][0], af[im][1], af[im][2], af[im][3],
                      sA + 4u*(aBase + im*16*BKp + ks));
            unsigned bf[NT][2];
            #pragma unroll
            for (int jp = 0; jp < NT/2; ++jp) {
                unsigned r0, r1, r2, r3;
                ldsm4(r0, r1, r2, r3, sB + 4u*(bBase + jp*16*BKp + ks));
                bf[2*jp][0] = r0; bf[2*jp][1] = r1;
                bf[2*jp+1][0] = r2; bf[2*jp+1][1] = r3;
            }
            #pragma unroll
            for (int im = 0; im < MT; ++im)
                #pragma unroll
                for (int jn = 0; jn < NT; ++jn)
                    mma_tf32(acc[im][jn], af[im], bf[jn]);
        }
    };

    gload(0);
    sstore(0);
    __syncthreads();

    for (int kt = 0; kt < ktiles; ++kt) {
        const bool more = (kt + 1 < ktiles);
        if (more) gload((kt+1)*BK);
        compute(kt & 1);
        if (more) sstore((kt+1) & 1);
        __syncthreads();
    }

    #pragma unroll
    for (int im = 0; im < MT; ++im) {
        #pragma unroll
        for (int jn = 0; jn < NT; ++jn) {
            #pragma unroll
            for (int h = 0; h < 2; ++h) {
                const int m = m0 + mw0 + im*16 + qr + h*8;
                const int n = n0 + nw0 + jn*8 + qc*2;
                const long ci = (long)m * ldc + n;
                float v0 = acc[im][jn][h*2 + 0];
                float v1 = acc[im][jn][h*2 + 1];
                if (MODE == 0) {
                    C[ci] = v0; C[ci+1] = v1;
                } else if (MODE == 5) {
                    C[ci]   = 0.5f * v0 * (1.f + erff(v0 * 0.70710678118654752f));
                    C[ci+1] = 0.5f * v1 * (1.f + erff(v1 * 0.70710678118654752f));
                } else if (MODE == 6) {
                    C[ci]   = P1[ci]   * v0 + P2[ci];
                    C[ci+1] = P1[ci+1] * v1 + P2[ci+1];
                } else if (MODE == 7) {
                    C[ci] = v0; C[ci+1] = v1;
                    __nv_bfloat16* Cb = (__nv_bfloat16*)P2;
                    *(__nv_bfloat162*)(Cb + ci) = __floats2bfloat162_rn(v0, v1);
                } else if (MODE == 8) {
                    float2 p = *(const float2*)(P1 + ci);
                    C[ci]   = v0 - p.x;
                    C[ci+1] = v1 - p.y;
                }
            }
        }
    }
}

// ---------------- pipelined bf16 core (cp.async, 4 stages) ----------
// Tile (MW*32) x 64, MW*64 threads, warps (MW m) x (2 n), warp tile 32x32.
// OPA: 0 = A[M,K]; 2 = dual-source rows. OPB: 0 = B[N,K]; 1 = B[K,N].
// MODE: 2 tril mask  3 C=P1a-ETA*acc (tril-K)  8 C=P1dual-ETA*acc  9 C+=acc & bf16->Ch
template<int MW,int OPA,int OPB,int MODE,int OUTT>
__device__ __forceinline__ void hcore(
    int m0, int n0,
    const __nv_bfloat16* A, const __nv_bfloat16* A2, long lda,
    const __nv_bfloat16* B, long ldb,
    float* C, __nv_bfloat16* Ch, long ldc, int K,
    const float* P1a, const float* P1b, char* sm)
{
    constexpr int BM = MW*32, BK = 16;
    constexpr int ASTG = BM*48;
    constexpr int STG  = ASTG + 3072;
    const int tid = threadIdx.x, lane = tid & 31, wid = tid >> 5;
    const int wm = wid >> 1, wn = wid & 1;
    const int mw0 = wm * 32, nw0 = wn * 32;
    const int qr = lane >> 2, qc = lane & 3;
    const uint32_t sbase = smem_u32(sm);

    float acc[2][4][4];
    #pragma unroll
    for (int i = 0; i < 2; ++i)
        #pragma unroll
        for (int j = 0; j < 4; ++j)
            #pragma unroll
            for (int q = 0; q < 4; ++q) acc[i][j][q] = 0.f;

    int Kl = K;
    if (MODE == 3) { int t = m0 + BM; Kl = t < K ? t : K; }
    const int ktiles = Kl / BK;

    const int arow = tid >> 1, ahalf = tid & 1;    // blockDim == BM*2
    const int mg = m0 + arow;
    const __nv_bfloat16* Ar;
    if (OPA == 2) Ar = (mg < RR) ? (A + (long)mg * lda)
                                 : (A2 + (long)(mg - RR) * lda);
    else          Ar = A + (long)mg * lda;

    auto fill = [&](int kt) {
        if (kt < ktiles) {
            const long k0 = (long)kt * BK;
            const uint32_t as = sbase + (kt & 3) * STG;
            const uint32_t bs = as + ASTG;
            cpa16(as + arow*48 + ahalf*16, Ar + k0 + ahalf*8);
            if (MW == 2 || tid < 128) {
                if (OPB == 0) {
                    const int r = tid >> 1, h = tid & 1;
                    cpa16(bs + (r & 63)*48 + h*16, B + (long)(n0 + (r & 63))*ldb + k0 + h*8);
                } else {
                    const int kk = (tid >> 3) & 15, nc = tid & 7;
                    cpa16(bs + kk*144 + nc*16, B + (k0 + kk)*ldb + n0 + nc*8);
                }
            }
        }
        cpa_commit();
    };
    auto compute = [&](int kt) {
        const uint32_t sA = sbase + (kt & 3) * STG;
        const uint32_t sB = sA + ASTG;
        const int g = lane >> 3;
        unsigned af[2][4];
        #pragma unroll
        for (int im = 0; im < 2; ++im) {
            const int row = mw0 + im*16 + (g & 1)*8 + (lane & 7);
            const int kb = (g >> 1)*8;
            ldsm4(af[im][0], af[im][1], af[im][2], af[im][3],
                  sA + (unsigned)(row*48 + kb*2));
        }
        unsigned bf[4][2];
        #pragma unroll
        for (int jp = 0; jp < 2; ++jp) {
            unsigned r0, r1, r2, r3;
            if (OPB == 0) {
                const int row = nw0 + jp*16 + (g >> 1)*8 + (lane & 7);
                const int kb = (g & 1)*8;
                ldsm4(r0, r1, r2, r3, sB + (unsigned)(row*48 + kb*2));
            } else {
                const int krow = (g & 1)*8 + (lane & 7);
                const int col = nw0 + jp*16 + (g >> 1)*8;
                ldsm4t(r0, r1, r2, r3, sB + (unsigned)(krow*144 + col*2));
            }
            bf[2*jp][0] = r0; bf[2*jp][1] = r1;
            bf[2*jp+1][0] = r2; bf[2*jp+1][1] = r3;
        }
        #pragma unroll
        for (int im = 0; im < 2; ++im)
            #pragma unroll
            for (int jn = 0; jn < 4; ++jn)
                mma_bf16(acc[im][jn], af[im], bf[jn]);
    };

    fill(0); fill(1); fill(2);
    for (int kt = 0; kt < ktiles; ++kt) {
        asm volatile("cp.async.wait_group 2;" ::: "memory");
        __syncthreads();
        fill(kt + 3);
        compute(kt);
    }
    asm volatile("cp.async.wait_group 0;" ::: "memory");

    #pragma unroll
    for (int im = 0; im < 2; ++im) {
        #pragma unroll
        for (int jn = 0; jn < 4; ++jn) {
            #pragma unroll
            for (int h = 0; h < 2; ++h) {
                const int m = m0 + mw0 + im*16 + qr + h*8;
                const int n = n0 + nw0 + jn*8 + qc*2;
                const long ci = (long)m * ldc + n;
                float v0 = acc[im][jn][h*2 + 0];
                float v1 = acc[im][jn][h*2 + 1];
                if (MODE == 2) {
                    const bool z = ((n >> 4) > (m >> 4));
                    if (z) { v0 = 0.f; v1 = 0.f; }
                    if (OUTT == 1)
                        *(__nv_bfloat162*)(Ch + ci) = __floats2bfloat162_rn(v0, v1);
                    else { C[ci] = v0; C[ci+1] = v1; }
                } else if (MODE == 3) {
                    float2 p = *(const float2*)(P1a + (long)m * ldc + n);
                    C[ci]   = p.x - ETA_F * v0;
                    C[ci+1] = p.y - ETA_F * v1;
                } else if (MODE == 8) {
                    const float* Pp = (m < RR) ? (P1a + (long)m * ldc + n)
                                               : (P1b + (long)(m - RR) * ldc + n);
                    float2 p = *(const float2*)Pp;
                    C[ci]   = p.x - ETA_F * v0;
                    C[ci+1] = p.y - ETA_F * v1;
                } else if (MODE == 9) {
                    float2 c = *(const float2*)(C + ci);
                    float w0 = c.x + v0, w1 = c.y + v1;
                    C[ci] = w0; C[ci+1] = w1;
                    *(__nv_bfloat162*)(Ch + ci) = __floats2bfloat162_rn(w0, w1);
                }
            }
        }
    }
}

// Gram wrappers (batched over z, block-tril skip) — 128x64 tiles, 256 threads
template<int OUTT>
__global__ void __launch_bounds__(256) k_gram(
    const __nv_bfloat16* __restrict__ Aall, const __nv_bfloat16* __restrict__ Ball,
    float* __restrict__ Cf, __nv_bfloat16* __restrict__ Cbh)
{
    const int m0 = blockIdx.y * 128, n0 = blockIdx.x * 64;
    if (n0 >= m0 + 128) return;
    __shared__ __align__(16) char sm[4*(128*48 + 3072)];
    const long z = blockIdx.z;
    hcore<4,0,0,2,OUTT>(m0, n0,
        Aall + z*RR*DD, nullptr, DD, Ball + z*RR*DD, DD,
        (OUTT == 0) ? (Cf + z*RR*RR) : nullptr,
        (OUTT == 1) ? (Cbh + z*RR*RR) : nullptr,
        RR, DD, nullptr, nullptr, sm);
}

// chunk-loop kernels — 64x64 tiles, 128 threads (2+ CTAs/SM co-resident)
__global__ void __launch_bounds__(128) k_corr64(
    const __nv_bfloat16* __restrict__ TVhc, const __nv_bfloat16* __restrict__ PRhc,
    const __nv_bfloat16* __restrict__ UWh, float* __restrict__ AP,
    const float* __restrict__ ABc, const float* __restrict__ PBc)
{
    __shared__ __align__(16) char sm[4*(64*48 + 3072)];
    hcore<2,2,0,8,0>(blockIdx.y * 64, blockIdx.x * 64,
                     TVhc, PRhc, DD, UWh, DD, AP, nullptr, DD, DD, ABc, PBc, sm);
}

__global__ void __launch_bounds__(128) k_rduw64(
    const __nv_bfloat16* __restrict__ Hb, const __nv_bfloat16* __restrict__ Eh,
    float* __restrict__ OTc, const float* __restrict__ P0,
    const __nv_bfloat16* __restrict__ Eth, const __nv_bfloat16* __restrict__ TVhc,
    float* __restrict__ UW, __nv_bfloat16* __restrict__ UWh)
{
    __shared__ __align__(16) char sm[4*(64*48 + 3072)];
    const int n0 = blockIdx.x * 64;
    if (blockIdx.y < 8) {
        // readout: OT = P0 - ETA * trilHb @ E   (A=Hb [RR,RR], B=Eh [RR,DD])
        hcore<2,0,1,3,0>(blockIdx.y * 64, n0, Hb, nullptr, RR, Eh, DD,
                         OTc, nullptr, DD, RR, P0, nullptr, sm);
    } else {
        // UW += E^T @ TVc   (A=Eth [DD,RR], B=TVhc [RR,DD])
        hcore<2,0,1,9,0>((blockIdx.y - 8) * 64, n0, Eth, nullptr, RR, TVhc, DD,
                         UW, UWh, DD, RR, nullptr, nullptr, sm);
    }
}

// ---------------- host side ----------------
extern "C" void kernel_launch(void* const* d_in, const int* in_sizes, int n_in,
                              void* d_out, int out_size) {
    const float* x      = (const float*)d_in[0];
    const float* noise  = (const float*)d_in[1];
    const float* alpha1 = (const float*)d_in[2];
    const float* alpha2 = (const float*)d_in[3];
    const float* W_map  = (const float*)d_in[4];
    const float* W_st   = (const float*)d_in[5];
    const float* W_pr   = (const float*)d_in[6];
    const float* W_p1   = (const float*)d_in[7];
    const float* W_p2   = (const float*)d_in[8];
    float* out = (float*)d_out;

    float *HT, *ST, *TV, *PR, *AB, *PB, *OT, *X1, *H2, *U, *UW, *AP, *Gb;
    __nv_bfloat16 *UWh, *TVh, *PRh, *Eh, *Eth, *Hbh;
    cudaGetSymbolAddress((void**)&HT, g_HT);
    cudaGetSymbolAddress((void**)&ST, g_STATE);
    cudaGetSymbolAddress((void**)&TV, g_TV);
    cudaGetSymbolAddress((void**)&PR, g_PROBE);
    cudaGetSymbolAddress((void**)&AB, g_ABASE);
    cudaGetSymbolAddress((void**)&PB, g_PBASE);
    cudaGetSymbolAddress((void**)&OT, g_OT);
    cudaGetSymbolAddress((void**)&X1, g_X1);
    cudaGetSymbolAddress((void**)&H2, g_H2);
    cudaGetSymbolAddress((void**)&U,  g_U);
    cudaGetSymbolAddress((void**)&UW, g_UW);
    cudaGetSymbolAddress((void**)&AP, g_AP);
    cudaGetSymbolAddress((void**)&Gb, g_Gb);
    cudaGetSymbolAddress((void**)&UWh, g_UWh);
    cudaGetSymbolAddress((void**)&TVh, g_TVh);
    cudaGetSymbolAddress((void**)&PRh, g_PRh);
    cudaGetSymbolAddress((void**)&Eh,  g_Eh);
    cudaGetSymbolAddress((void**)&Eth, g_Eth);
    cudaGetSymbolAddress((void**)&Hbh, g_Hbh);

    const int EW_BLKS = (SB*DD/4) / 256;

    // 0: h = tanh(alpha1*x), time-major
    k_prep<<<EW_BLKS, 256>>>(x, alpha1, HT);
    // 1: STATE = HT@Wst^T (tf32)
    gemm_t<128,128,2,4,0><<<dim3(DD/128, SB/128), 256>>>(
        HT, DD, W_st, DD, ST, DD, DD, nullptr, nullptr);
    // 2: TV = STATE + noise (fp32 + bf16)
    k_tv<<<EW_BLKS, 256>>>(ST, noise, TV, TVh);
    // 3: batched block-tril Gram (pipelined bf16)
    k_gram<0><<<dim3(RR/64, RR/128, NC), 256>>>(TVh, TVh, Gb, nullptr);
    // 4: PROBE = HT@Wpr^T (tf32 + bf16 copy)
    gemm_t<128,128,2,4,7><<<dim3(DD/128, SB/128), 256>>>(
        HT, DD, W_pr, DD, PR, DD, DD, nullptr, (const float*)PRh);
    // 5: ABASE = TV@W0^T - STATE (tf32)
    gemm_t<128,128,2,4,8><<<dim3(DD/128, SB/128), 256>>>(
        TV, DD, W_map, DD, AB, DD, DD, ST, nullptr);
    // 6: PBASE = PROBE@W0^T (tf32)
    gemm_t<128,128,2,4,0><<<dim3(DD/128, SB/128), 256>>>(
        PR, DD, W_map, DD, PB, DD, DD, nullptr, nullptr);
    // 7: cross-Gram -> Hbh (bf16)
    k_gram<1><<<dim3(RR/64, RR/128, NC), 256>>>(PRh, TVh, nullptr, Hbh);
    // 8: zero UW accumulator
    k_zero<<<(DD*DD/4)/256, 256>>>(UW, UWh);

    // chunk loop — 64x64 tiles, 2+ CTAs/SM
    for (int c = 0; c < NC; ++c) {
        const __nv_bfloat16* TVhc = TVh + (long)c*RR*DD;
        const __nv_bfloat16* PRhc = PRh + (long)c*RR*DD;
        const float* ABc = AB + (long)c*RR*DD;
        const float* PBc = PB + (long)c*RR*DD;
        const float* Asolve;
        const float* P0ptr;
        if (c == 0) {
            Asolve = ABc;
            P0ptr  = PBc;
        } else {
            k_corr64<<<dim3(DD/64, (2*RR)/64), 128>>>(TVhc, PRhc, UWh, AP, ABc, PBc);
            Asolve = AP;
            P0ptr  = AP + (long)RR*DD;
        }
        solve_k<<<DD/16, 256>>>(Asolve, Gb + (long)c*RR*RR, Eh, Eth);
        k_rduw64<<<dim3(DD/64, 24), 128>>>(Hbh + (long)c*RR*RR, Eh,
                                           OT + (long)c*RR*DD, P0ptr,
                                           Eth, TVhc, UW, UWh);
    }

    // x1 / h2
    k_x1h2<<<EW_BLKS, 256>>>(OT, x, alpha2, X1, H2);
    // U = gelu(h2 @ Wp1^T)   (tf32)
    gemm_t<128,128,2,4,5><<<dim3(DD/128, SB/128), 256>>>(
        H2, DD, W_p1, DD, U, DD, DD, nullptr, nullptr);
    // out = U * (h2 @ Wp2^T) + X1   (tf32)
    gemm_t<128,128,2,4,6><<<dim3(DD/128, SB/128), 256>>>(
        H2, DD, W_p2, DD, out, DD, DD, U, X1);
}

// round 12
// speedup vs baseline: 3.0798x; 2.9420x over previous
#include <cuda_runtime.h>
#include <cuda_bf16.h>
#include <math.h>
#include <stdint.h>

#define BB 16
#define SS 1024
#define DD 1024
#define CH 32
#define RR 512            // CH*BB rows per chunk
#define NC 32             // SS/CH chunks
#define SB (SS*BB)        // 16384 rows total
#define ETA_F (0.01f*2.0f/(16.0f*1024.0f))

// ---------------- device scratch ----------------
__device__ float g_HT[SB*DD];
__device__ float g_STATE[SB*DD];
__device__ float g_PROBE[SB*DD];
__device__ float g_PBASE[SB*DD];   // PROBE@W0^T (all chunks)
__device__ float g_OT[SB*DD];
__device__ float g_X1[SB*DD];
__device__ float g_H2[SB*DD];
__device__ float g_U[SB*DD];
__device__ float g_UW[DD*DD];      // accumulated A^T TV (fp32 master)
__device__ float g_P[RR*DD];       // per-chunk corrected P (fp32)
__device__ __nv_bfloat16 g_HTh[SB*DD];
__device__ __nv_bfloat16 g_TVh[SB*DD];
__device__ __nv_bfloat16 g_ABh[SB*DD];   // base A = TV@W0^T - STATE (bf16)
__device__ __nv_bfloat16 g_PRh[SB*DD];
__device__ __nv_bfloat16 g_UWh[DD*DD];
__device__ __nv_bfloat16 g_Wsth[DD*DD];
__device__ __nv_bfloat16 g_W0h[DD*DD];
__device__ __nv_bfloat16 g_Ah[RR*DD];    // corrected A (bf16, row-major)
__device__ __nv_bfloat16 g_Ath[DD*RR];   // corrected A transposed
__device__ __nv_bfloat16 g_Hbh[(long)NC*RR*RR];

// ---------------- helpers ----------------
__device__ __forceinline__ float tf32r(float x) {
    unsigned u;
    asm("cvt.rna.tf32.f32 %0, %1;" : "=r"(u) : "f"(x));
    return __uint_as_float(u);
}
__device__ __forceinline__ uint32_t smem_u32(const void* p) {
    uint32_t a;
    asm("{ .reg .u64 t; cvta.to.shared.u64 t, %1; cvt.u32.u64 %0, t; }"
        : "=r"(a) : "l"(p));
    return a;
}
__device__ __forceinline__ void cpa16(uint32_t d, const void* g) {
    asm volatile("cp.async.cg.shared.global [%0], [%1], 16;" :: "r"(d), "l"(g));
}
__device__ __forceinline__ void cpa_commit() {
    asm volatile("cp.async.commit_group;" ::: "memory");
}
__device__ __forceinline__ void mma_tf32(float* c, const unsigned* a, const unsigned* b) {
    asm volatile(
        "mma.sync.aligned.m16n8k8.row.col.f32.tf32.tf32.f32 "
        "{%0,%1,%2,%3}, {%4,%5,%6,%7}, {%8,%9}, {%0,%1,%2,%3};\n"
        : "+f"(c[0]), "+f"(c[1]), "+f"(c[2]), "+f"(c[3])
        : "r"(a[0]), "r"(a[1]), "r"(a[2]), "r"(a[3]), "r"(b[0]), "r"(b[1]));
}
__device__ __forceinline__ void mma_bf16(float* c, const unsigned* a, const unsigned* b) {
    asm volatile(
        "mma.sync.aligned.m16n8k16.row.col.f32.bf16.bf16.f32 "
        "{%0,%1,%2,%3}, {%4,%5,%6,%7}, {%8,%9}, {%0,%1,%2,%3};\n"
        : "+f"(c[0]), "+f"(c[1]), "+f"(c[2]), "+f"(c[3])
        : "r"(a[0]), "r"(a[1]), "r"(a[2]), "r"(a[3]), "r"(b[0]), "r"(b[1]));
}
__device__ __forceinline__ void ldsm4(unsigned& r0, unsigned& r1, unsigned& r2,
                                      unsigned& r3, unsigned addr) {
    asm volatile("ldmatrix.sync.aligned.m8n8.x4.shared.b16 {%0,%1,%2,%3},[%4];"
                 : "=r"(r0), "=r"(r1), "=r"(r2), "=r"(r3) : "r"(addr));
}
__device__ __forceinline__ void ldsm4t(unsigned& r0, unsigned& r1, unsigned& r2,
                                       unsigned& r3, unsigned addr) {
    asm volatile("ldmatrix.sync.aligned.m8n8.x4.trans.shared.b16 {%0,%1,%2,%3},[%4];"
                 : "=r"(r0), "=r"(r1), "=r"(r2), "=r"(r3) : "r"(addr));
}

// ---------------- elementwise kernels ----------------
__global__ void k_cvt(const float* __restrict__ a, __nv_bfloat16* __restrict__ ah,
                      const float* __restrict__ b, __nv_bfloat16* __restrict__ bh) {
    long i = (long)blockIdx.x * blockDim.x + threadIdx.x;
    float4 v = *(const float4*)(a + i*4);
    *(__nv_bfloat162*)(ah + i*4)     = __floats2bfloat162_rn(v.x, v.y);
    *(__nv_bfloat162*)(ah + i*4 + 2) = __floats2bfloat162_rn(v.z, v.w);
    float4 w = *(const float4*)(b + i*4);
    *(__nv_bfloat162*)(bh + i*4)     = __floats2bfloat162_rn(w.x, w.y);
    *(__nv_bfloat162*)(bh + i*4 + 2) = __floats2bfloat162_rn(w.z, w.w);
}

__global__ void k_prep(const float* __restrict__ x, const float* __restrict__ a1,
                       float* __restrict__ HT, __nv_bfloat16* __restrict__ HTh) {
    long i4 = (long)blockIdx.x * blockDim.x + threadIdx.x;
    long flat = i4 * 4;
    int b = (int)(flat / ((long)SS*DD));
    int t = (int)((flat / DD) % SS);
    int d = (int)(flat % DD);
    float4 xv = *(const float4*)(x + flat);
    float4 av = *(const float4*)(a1 + d);
    float4 o;
    o.x = tanhf(av.x * xv.x); o.y = tanhf(av.y * xv.y);
    o.z = tanhf(av.z * xv.z); o.w = tanhf(av.w * xv.w);
    const long di = (long)(t*BB + b) * DD + d;
    *(float4*)(HT + di) = o;
    *(__nv_bfloat162*)(HTh + di)     = __floats2bfloat162_rn(o.x, o.y);
    *(__nv_bfloat162*)(HTh + di + 2) = __floats2bfloat162_rn(o.z, o.w);
}

__global__ void k_tv(const float* __restrict__ ST, const float* __restrict__ noise,
                     __nv_bfloat16* __restrict__ TVh) {
    long i4 = (long)blockIdx.x * blockDim.x + threadIdx.x;
    long flat = i4 * 4;
    int t = (int)(flat / ((long)BB*DD));
    int b = (int)((flat / DD) % BB);
    int d = (int)(flat % DD);
    float4 s = *(const float4*)(ST + flat);
    float4 n = *(const float4*)(noise + ((long)b*SS + t) * DD + d);
    *(__nv_bfloat162*)(TVh + flat)     = __floats2bfloat162_rn(s.x+n.x, s.y+n.y);
    *(__nv_bfloat162*)(TVh + flat + 2) = __floats2bfloat162_rn(s.z+n.z, s.w+n.w);
}

__global__ void k_zero(float* __restrict__ a, __nv_bfloat16* __restrict__ ah) {
    long i = (long)blockIdx.x * blockDim.x + threadIdx.x;
    *(float4*)(a + i*4) = make_float4(0.f, 0.f, 0.f, 0.f);
    *(float2*)((float*)(ah + i*4)) = make_float2(0.f, 0.f);
}

__global__ void k_x1h2(const float* __restrict__ OT, const float* __restrict__ x,
                       const float* __restrict__ a2,
                       float* __restrict__ X1, float* __restrict__ H2) {
    long i4 = (long)blockIdx.x * blockDim.x + threadIdx.x;
    long flat = i4 * 4;
    int b = (int)(flat / ((long)SS*DD));
    int t = (int)((flat / DD) % SS);
    int d = (int)(flat % DD);
    float4 ro = *(const float4*)(OT + ((long)(t*BB + b) * DD + d));
    float4 xv = *(const float4*)(x + flat);
    float4 av = *(const float4*)(a2 + d);
    float4 x1; x1.x = ro.x+xv.x; x1.y = ro.y+xv.y; x1.z = ro.z+xv.z; x1.w = ro.w+xv.w;
    *(float4*)(X1 + flat) = x1;
    float4 h; h.x = tanhf(av.x*x1.x); h.y = tanhf(av.y*x1.y);
    h.z = tanhf(av.z*x1.z); h.w = tanhf(av.w*x1.w);
    *(float4*)(H2 + flat) = h;
}

// ---------------- tf32 tensor-core GEMM (direct-precision paths) ----------
// MODE: 0 plain  5 gelu  6 C=P1*acc+P2  7 plain + bf16 copy->P2
template<int BM,int BN,int MW,int NW,int MODE>
__global__ void __launch_bounds__(MW*NW*32, 2)
gemm_t(const float* __restrict__ A, int lda,
       const float* __restrict__ B, int ldb,
       float* __restrict__ C, int ldc, int K,
       const float* __restrict__ P1, const float* __restrict__ P2)
{
    constexpr int BK  = 16;
    constexpr int BKp = 20;
    constexpr int T   = MW*NW*32;
    constexpr int WM  = BM/MW, WN = BN/NW;
    constexpr int MT  = WM/16, NT = WN/8;
    constexpr int LPA = BM*BK/(4*T);
    constexpr int LPB = BN*BK/(4*T);

    const int m0 = blockIdx.y * BM, n0 = blockIdx.x * BN;

    __shared__ __align__(16) float As[2][BM][BKp];
    __shared__ __align__(16) float Bs[2][BN][BKp];

    const int tid  = threadIdx.x;
    const int lane = tid & 31;
    const int wid  = tid >> 5;
    const int wm   = wid / NW, wn = wid % NW;
    const int mw0  = wm * WM, nw0 = wn * WN;
    const int qr   = lane >> 2;
    const int qc   = lane & 3;
    const int lr   = lane & 7;
    const int aBase = (mw0 + lr + ((lane>>3)&1)*8) * BKp + ((lane>>4)&1)*4;
    const int bBase = (nw0 + lr + ((lane>>4)&1)*8) * BKp + ((lane>>3)&1)*4;

    float acc[MT][NT][4];
    #pragma unroll
    for (int i = 0; i < MT; ++i)
        #pragma unroll
        for (int j = 0; j < NT; ++j)
            #pragma unroll
            for (int q = 0; q < 4; ++q) acc[i][j][q] = 0.f;

    const int ktiles = K / BK;
    float4 pa[LPA], pb[LPB];

    auto gload = [&](int k0) {
        #pragma unroll
        for (int p = 0; p < LPA; ++p) {
            const int idx = tid + p*T;
            const int am = idx / (BK/4), akq = idx % (BK/4);
            pa[p] = *(const float4*)(A + (long)(m0 + am) * lda + k0 + 4*akq);
        }
        #pragma unroll
        for (int p = 0; p < LPB; ++p) {
            const int idx = tid + p*T;
            const int bn = idx / (BK/4), bkq = idx % (BK/4);
            pb[p] = *(const float4*)(B + (long)(n0 + bn) * ldb + k0 + 4*bkq);
        }
    };
    auto sstore = [&](int s) {
        #pragma unroll
        for (int p = 0; p < LPA; ++p) {
            const int idx = tid + p*T;
            const int am = idx / (BK/4), akq = idx % (BK/4);
            float4 w = make_float4(tf32r(pa[p].x), tf32r(pa[p].y),
                                   tf32r(pa[p].z), tf32r(pa[p].w));
            *(float4*)&As[s][am][4*akq] = w;
        }
        #pragma unroll
        for (int p = 0; p < LPB; ++p) {
            const int idx = tid + p*T;
            const int bn = idx / (BK/4), bkq = idx % (BK/4);
            float4 w = make_float4(tf32r(pb[p].x), tf32r(pb[p].y),
                                   tf32r(pb[p].z), tf32r(pb[p].w));
            *(float4*)&Bs[s][bn][4*bkq] = w;
        }
    };
    auto compute = [&](int s) {
        const unsigned sA = (unsigned)__cvta_generic_to_shared(&As[s][0][0]);
        const unsigned sB = (unsigned)__cvta_generic_to_shared(&Bs[s][0][0]);
        #pragma unroll
        for (int ks = 0; ks < BK; ks += 8) {
            unsigned af[MT][4];
            #pragma unroll
            for (int im = 0; im < MT; ++im)
                ldsm4(af[im][0], af[im][1], af[im][2], af[im][3],
                      sA + 4u*(aBase + im*16*BKp + ks));
            unsigned bf[NT][2];
            #pragma unroll
            for (int jp = 0; jp < NT/2; ++jp) {
                unsigned r0, r1, r2, r3;
                ldsm4(r0, r1, r2, r3, sB + 4u*(bBase + jp*16*BKp + ks));
                bf[2*jp][0] = r0; bf[2*jp][1] = r1;
                bf[2*jp+1][0] = r2; bf[2*jp+1][1] = r3;
            }
            #pragma unroll
            for (int im = 0; im < MT; ++im)
                #pragma unroll
                for (int jn = 0; jn < NT; ++jn)
                    mma_tf32(acc[im][jn], af[im], bf[jn]);
        }
    };

    gload(0);
    sstore(0);
    __syncthreads();

    for (int kt = 0; kt < ktiles; ++kt) {
        const bool more = (kt + 1 < ktiles);
        if (more) gload((kt+1)*BK);
        compute(kt & 1);
        if (more) sstore((kt+1) & 1);
        __syncthreads();
    }

    #pragma unroll
    for (int im = 0; im < MT; ++im) {
        #pragma unroll
        for (int jn = 0; jn < NT; ++jn) {
            #pragma unroll
            for (int h = 0; h < 2; ++h) {
                const int m = m0 + mw0 + im*16 + qr + h*8;
                const int n = n0 + nw0 + jn*8 + qc*2;
                const long ci = (long)m * ldc + n;
                float v0 = acc[im][jn][h*2 + 0];
                float v1 = acc[im][jn][h*2 + 1];
                if (MODE == 0) {
                    C[ci] = v0; C[ci+1] = v1;
                } else if (MODE == 5) {
                    C[ci]   = 0.5f * v0 * (1.f + erff(v0 * 0.70710678118654752f));
                    C[ci+1] = 0.5f * v1 * (1.f + erff(v1 * 0.70710678118654752f));
                } else if (MODE == 6) {
                    C[ci]   = P1[ci]   * v0 + P2[ci];
                    C[ci+1] = P1[ci+1] * v1 + P2[ci+1];
                } else if (MODE == 7) {
                    C[ci] = v0; C[ci+1] = v1;
                    __nv_bfloat16* Cb = (__nv_bfloat16*)P2;
                    *(__nv_bfloat162*)(Cb + ci) = __floats2bfloat162_rn(v0, v1);
                }
            }
        }
    }
}

// ---------------- pipelined bf16 core (cp.async, 4 stages) ----------
// Tile (MW*32) x 64, MW*64 threads, warps (MW m) x (2 n), warp tile 32x32.
// OPA: 0 = A[M,K]; 2 = dual-source rows. OPB: 0 = B[N,K]; 1 = B[K,N].
// MODE: 2 tril mask -> bf16 Ch     3 C=P1a-ETA*acc (tril-K)
//       9 C+=acc & bf16->Ch        10 corr: A rows -> Ch/Ct bf16 (base=Bb),
//                                      P rows -> C fp32 (base=P1b)
//       11 Ch = bf16(acc - P1a)    12 C = acc (fp32)
template<int MW,int OPA,int OPB,int MODE>
__device__ __forceinline__ void hcore(
    int m0, int n0,
    const __nv_bfloat16* A, const __nv_bfloat16* A2, long lda,
    const __nv_bfloat16* B, long ldb,
    float* C, __nv_bfloat16* Ch, __nv_bfloat16* Ct, long ldc, int K,
    const float* P1a, const float* P1b, const __nv_bfloat16* Bb, char* sm)
{
    constexpr int BM = MW*32, BK = 16;
    constexpr int ASTG = BM*48;
    constexpr int STG  = ASTG + 3072;
    const int tid = threadIdx.x, lane = tid & 31, wid = tid >> 5;
    const int wm = wid >> 1, wn = wid & 1;
    const int mw0 = wm * 32, nw0 = wn * 32;
    const int qr = lane >> 2, qc = lane & 3;
    const uint32_t sbase = smem_u32(sm);

    float acc[2][4][4];
    #pragma unroll
    for (int i = 0; i < 2; ++i)
        #pragma unroll
        for (int j = 0; j < 4; ++j)
            #pragma unroll
            for (int q = 0; q < 4; ++q) acc[i][j][q] = 0.f;

    int Kl = K;
    if (MODE == 3) { int t = m0 + BM; Kl = t < K ? t : K; }
    const int ktiles = Kl / BK;

    const int arow = tid >> 1, ahalf = tid & 1;    // blockDim == BM*2
    const int mg = m0 + arow;
    const __nv_bfloat16* Ar;
    if (OPA == 2) Ar = (mg < RR) ? (A + (long)mg * lda)
                                 : (A2 + (long)(mg - RR) * lda);
    else          Ar = A + (long)mg * lda;

    auto fill = [&](int kt) {
        if (kt < ktiles) {
            const long k0 = (long)kt * BK;
            const uint32_t as = sbase + (kt & 3) * STG;
            const uint32_t bs = as + ASTG;
            cpa16(as + arow*48 + ahalf*16, Ar + k0 + ahalf*8);
            if (MW == 2 || tid < 128) {
                if (OPB == 0) {
                    const int r = tid >> 1, h = tid & 1;
                    cpa16(bs + (r & 63)*48 + h*16, B + (long)(n0 + (r & 63))*ldb + k0 + h*8);
                } else {
                    const int kk = (tid >> 3) & 15, nc = tid & 7;
                    cpa16(bs + kk*144 + nc*16, B + (k0 + kk)*ldb + n0 + nc*8);
                }
            }
        }
        cpa_commit();
    };
    auto compute = [&](int kt) {
        const uint32_t sA = sbase + (kt & 3) * STG;
        const uint32_t sB = sA + ASTG;
        const int g = lane >> 3;
        unsigned af[2][4];
        #pragma unroll
        for (int im = 0; im < 2; ++im) {
            const int row = mw0 + im*16 + (g & 1)*8 + (lane & 7);
            const int kb = (g >> 1)*8;
            ldsm4(af[im][0], af[im][1], af[im][2], af[im][3],
                  sA + (unsigned)(row*48 + kb*2));
        }
        unsigned bf[4][2];
        #pragma unroll
        for (int jp = 0; jp < 2; ++jp) {
            unsigned r0, r1, r2, r3;
            if (OPB == 0) {
                const int row = nw0 + jp*16 + (g >> 1)*8 + (lane & 7);
                const int kb = (g & 1)*8;
                ldsm4(r0, r1, r2, r3, sB + (unsigned)(row*48 + kb*2));
            } else {
                const int krow = (g & 1)*8 + (lane & 7);
                const int col = nw0 + jp*16 + (g >> 1)*8;
                ldsm4t(r0, r1, r2, r3, sB + (unsigned)(krow*144 + col*2));
            }
            bf[2*jp][0] = r0; bf[2*jp][1] = r1;
            bf[2*jp+1][0] = r2; bf[2*jp+1][1] = r3;
        }
        #pragma unroll
        for (int im = 0; im < 2; ++im)
            #pragma unroll
            for (int jn = 0; jn < 4; ++jn)
                mma_bf16(acc[im][jn], af[im], bf[jn]);
    };

    fill(0); fill(1); fill(2);
    for (int kt = 0; kt < ktiles; ++kt) {
        asm volatile("cp.async.wait_group 2;" ::: "memory");
        __syncthreads();
        fill(kt + 3);
        compute(kt);
    }
    asm volatile("cp.async.wait_group 0;" ::: "memory");

    #pragma unroll
    for (int im = 0; im < 2; ++im) {
        #pragma unroll
        for (int jn = 0; jn < 4; ++jn) {
            #pragma unroll
            for (int h = 0; h < 2; ++h) {
                const int m = m0 + mw0 + im*16 + qr + h*8;
                const int n = n0 + nw0 + jn*8 + qc*2;
                const long ci = (long)m * ldc + n;
                float v0 = acc[im][jn][h*2 + 0];
                float v1 = acc[im][jn][h*2 + 1];
                if (MODE == 2) {
                    const bool z = ((n >> 4) > (m >> 4));
                    if (z) { v0 = 0.f; v1 = 0.f; }
                    *(__nv_bfloat162*)(Ch + ci) = __floats2bfloat162_rn(v0, v1);
                } else if (MODE == 3) {
                    float2 p = *(const float2*)(P1a + (long)m * ldc + n);
                    C[ci]   = p.x - ETA_F * v0;
                    C[ci+1] = p.y - ETA_F * v1;
                } else if (MODE == 9) {
                    float2 c = *(const float2*)(C + ci);
                    float w0 = c.x + v0, w1 = c.y + v1;
                    C[ci] = w0; C[ci+1] = w1;
                    *(__nv_bfloat162*)(Ch + ci) = __floats2bfloat162_rn(w0, w1);
                } else if (MODE == 10) {
                    if (m < RR) {
                        float b0 = __bfloat162float(Bb[(long)m * DD + n]);
                        float b1 = __bfloat162float(Bb[(long)m * DD + n + 1]);
                        float w0 = b0 - ETA_F * v0, w1 = b1 - ETA_F * v1;
                        *(__nv_bfloat162*)(Ch + (long)m * DD + n) =
                            __floats2bfloat162_rn(w0, w1);
                        Ct[(long)n * RR + m]       = __float2bfloat16(w0);
                        Ct[(long)(n + 1) * RR + m] = __float2bfloat16(w1);
                    } else {
                        const long pi = (long)(m - RR) * DD + n;
                        float2 p = *(const float2*)(P1b + pi);
                        C[pi]     = p.x - ETA_F * v0;
                        C[pi + 1] = p.y - ETA_F * v1;
                    }
                } else if (MODE == 11) {
                    float2 p = *(const float2*)(P1a + ci);
                    *(__nv_bfloat162*)(Ch + ci) =
                        __floats2bfloat162_rn(v0 - p.x, v1 - p.y);
                } else if (MODE == 12) {
                    C[ci] = v0; C[ci+1] = v1;
                }
            }
        }
    }
}

// STATE = HTh @ Wsth^T (fp32 out)
__global__ void __launch_bounds__(256) k_bstate(
    const __nv_bfloat16* __restrict__ HTh, const __nv_bfloat16* __restrict__ Wsth,
    float* __restrict__ ST)
{
    __shared__ __align__(16) char sm[4*(128*48 + 3072)];
    hcore<4,0,0,12>(blockIdx.y * 128, blockIdx.x * 64, HTh, nullptr, DD,
                    Wsth, DD, ST, nullptr, nullptr, DD, DD,
                    nullptr, nullptr, nullptr, sm);
}

// ABh = bf16(TVh @ W0h^T - ST)
__global__ void __launch_bounds__(256) k_babh(
    const __nv_bfloat16* __restrict__ TVh, const __nv_bfloat16* __restrict__ W0h,
    const float* __restrict__ ST, __nv_bfloat16* __restrict__ ABh)
{
    __shared__ __align__(16) char sm[4*(128*48 + 3072)];
    hcore<4,0,0,11>(blockIdx.y * 128, blockIdx.x * 64, TVh, nullptr, DD,
                    W0h, DD, nullptr, ABh, nullptr, DD, DD,
                    ST, nullptr, nullptr, sm);
}

// Hbh = bf16(trilblk(PRh @ TVh^T)), batched over chunks
__global__ void __launch_bounds__(256) k_gramh(
    const __nv_bfloat16* __restrict__ PRh, const __nv_bfloat16* __restrict__ TVh,
    __nv_bfloat16* __restrict__ Hbh)
{
    const int m0 = blockIdx.y * 128, n0 = blockIdx.x * 64;
    if (n0 >= m0 + 128) return;
    __shared__ __align__(16) char sm[4*(128*48 + 3072)];
    const long z = blockIdx.z;
    hcore<4,0,0,2>(m0, n0, PRh + z*RR*DD, nullptr, DD, TVh + z*RR*DD, DD,
                   nullptr, Hbh + z*RR*RR, nullptr, RR, DD,
                   nullptr, nullptr, nullptr, sm);
}

// corr: A rows -> Ah/Ath bf16 (base ABh - ETA*TV@UW^T),
//       P rows -> Pbuf fp32 (base PB - ETA*PR@UW^T)
__global__ void __launch_bounds__(128) k_corr64(
    const __nv_bfloat16* __restrict__ TVhc, const __nv_bfloat16* __restrict__ PRhc,
    const __nv_bfloat16* __restrict__ UWh, float* __restrict__ Pbuf,
    __nv_bfloat16* __restrict__ Ah, __nv_bfloat16* __restrict__ Ath,
    const __nv_bfloat16* __restrict__ ABhc, const float* __restrict__ PBc)
{
    __shared__ __align__(16) char sm[4*(64*48 + 3072)];
    hcore<2,2,0,10>(blockIdx.y * 64, blockIdx.x * 64,
                    TVhc, PRhc, DD, UWh, DD,
                    Pbuf, Ah, Ath, DD, DD, nullptr, PBc, ABhc, sm);
}

// merged readout (y<8) + UW update (y>=8)
__global__ void __launch_bounds__(128) k_rduw64(
    const __nv_bfloat16* __restrict__ Hb, const __nv_bfloat16* __restrict__ Ah,
    float* __restrict__ OTc, const float* __restrict__ Pbuf,
    const __nv_bfloat16* __restrict__ Ath, const __nv_bfloat16* __restrict__ TVhc,
    float* __restrict__ UW, __nv_bfloat16* __restrict__ UWh)
{
    __shared__ __align__(16) char sm[4*(64*48 + 3072)];
    const int n0 = blockIdx.x * 64;
    if (blockIdx.y < 8) {
        // OT = P - ETA * trilHb @ A
        hcore<2,0,1,3>(blockIdx.y * 64, n0, Hb, nullptr, RR, Ah, DD,
                       OTc, nullptr, nullptr, DD, RR,
                       Pbuf, nullptr, nullptr, sm);
    } else {
        // UW += A^T @ TVc
        hcore<2,0,1,9>((blockIdx.y - 8) * 64, n0, Ath, nullptr, RR, TVhc, DD,
                       UW, UWh, nullptr, DD, RR,
                       nullptr, nullptr, nullptr, sm);
    }
}

// ---------------- host side ----------------
extern "C" void kernel_launch(void* const* d_in, const int* in_sizes, int n_in,
                              void* d_out, int out_size) {
    const float* x      = (const float*)d_in[0];
    const float* noise  = (const float*)d_in[1];
    const float* alpha1 = (const float*)d_in[2];
    const float* alpha2 = (const float*)d_in[3];
    const float* W_map  = (const float*)d_in[4];
    const float* W_st   = (const float*)d_in[5];
    const float* W_pr   = (const float*)d_in[6];
    const float* W_p1   = (const float*)d_in[7];
    const float* W_p2   = (const float*)d_in[8];
    float* out = (float*)d_out;

    float *HT, *ST, *PR, *PB, *OT, *X1, *H2, *U, *UW, *Pbuf;
    __nv_bfloat16 *HTh, *TVh, *ABh, *PRh, *UWh, *Wsth, *W0h, *Ah, *Ath, *Hbh;
    cudaGetSymbolAddress((void**)&HT, g_HT);
    cudaGetSymbolAddress((void**)&ST, g_STATE);
    cudaGetSymbolAddress((void**)&PR, g_PROBE);
    cudaGetSymbolAddress((void**)&PB, g_PBASE);
    cudaGetSymbolAddress((void**)&OT, g_OT);
    cudaGetSymbolAddress((void**)&X1, g_X1);
    cudaGetSymbolAddress((void**)&H2, g_H2);
    cudaGetSymbolAddress((void**)&U,  g_U);
    cudaGetSymbolAddress((void**)&UW, g_UW);
    cudaGetSymbolAddress((void**)&Pbuf, g_P);
    cudaGetSymbolAddress((void**)&HTh, g_HTh);
    cudaGetSymbolAddress((void**)&TVh, g_TVh);
    cudaGetSymbolAddress((void**)&ABh, g_ABh);
    cudaGetSymbolAddress((void**)&PRh, g_PRh);
    cudaGetSymbolAddress((void**)&UWh, g_UWh);
    cudaGetSymbolAddress((void**)&Wsth, g_Wsth);
    cudaGetSymbolAddress((void**)&W0h, g_W0h);
    cudaGetSymbolAddress((void**)&Ah,  g_Ah);
    cudaGetSymbolAddress((void**)&Ath, g_Ath);
    cudaGetSymbolAddress((void**)&Hbh, g_Hbh);

    const int EW_BLKS = (SB*DD/4) / 256;

    // 0: bf16 weight copies
    k_cvt<<<(DD*DD/4)/256, 256>>>(W_st, Wsth, W_map, W0h);
    // 1: h = tanh(alpha1*x), time-major (fp32 + bf16)
    k_prep<<<EW_BLKS, 256>>>(x, alpha1, HT, HTh);
    // 2: zero UW
    k_zero<<<(DD*DD/4)/256, 256>>>(UW, UWh);
    // 3: STATE = HTh@Wsth^T (bf16 engine, fp32 out)   [profiled]
    k_bstate<<<dim3(DD/64, SB/128), 256>>>(HTh, Wsth, ST);
    // 4: TVh = bf16(STATE + noise)
    k_tv<<<EW_BLKS, 256>>>(ST, noise, TVh);
    // 5: ABh = bf16(TVh@W0h^T - STATE)
    k_babh<<<dim3(DD/64, SB/128), 256>>>(TVh, W0h, ST, ABh);
    // 6: PROBE = HT@Wpr^T (tf32, fp32 + bf16)
    gemm_t<128,128,2,4,7><<<dim3(DD/128, SB/128), 256>>>(
        HT, DD, W_pr, DD, PR, DD, DD, nullptr, (const float*)PRh);
    // 7: PBASE = PROBE@W0^T (tf32)
    gemm_t<128,128,2,4,0><<<dim3(DD/128, SB/128), 256>>>(
        PR, DD, W_map, DD, PB, DD, DD, nullptr, nullptr);
    // 8: cross-Gram -> Hbh
    k_gramh<<<dim3(RR/64, RR/128, NC), 256>>>(PRh, TVh, Hbh);

    // chunk loop — 2 bf16 GEMM launches per chunk, no solve
    for (int c = 0; c < NC; ++c) {
        const __nv_bfloat16* TVhc = TVh + (long)c*RR*DD;
        const __nv_bfloat16* PRhc = PRh + (long)c*RR*DD;
        k_corr64<<<dim3(DD/64, (2*RR)/64), 128>>>(
            TVhc, PRhc, UWh, Pbuf, Ah, Ath,
            ABh + (long)c*RR*DD, PB + (long)c*RR*DD);
        k_rduw64<<<dim3(DD/64, 24), 128>>>(
            Hbh + (long)c*RR*RR, Ah, OT + (long)c*RR*DD, Pbuf,
            Ath, TVhc, UW, UWh);
    }

    // x1 / h2
    k_x1h2<<<EW_BLKS, 256>>>(OT, x, alpha2, X1, H2);
    // U = gelu(h2 @ Wp1^T)   (tf32)
    gemm_t<128,128,2,4,5><<<dim3(DD/128, SB/128), 256>>>(
        H2, DD, W_p1, DD, U, DD, DD, nullptr, nullptr);
    // out = U * (h2 @ Wp2^T) + X1   (tf32)
    gemm_t<128,128,2,4,6><<<dim3(DD/128, SB/128), 256>>>(
        H2, DD, W_p2, DD, out, DD, DD, U, X1);
}